// round 10
// baseline (speedup 1.0000x reference)
#include <cuda_runtime.h>
#include <cuda_bf16.h>
#include <cstdint>

// Problem constants
#define Bn   64
#define Cn   256
#define HWn  1024
#define B2n  128      // 2*B
// TEMPERATURE = 0.5  -> logits = 2 * sim

// ---------------- scratch (static __device__, no allocation) ----------------
__device__ __align__(16) __nv_bfloat16 g_feats[(size_t)HWn * B2n * Cn]; // 64MB
__device__ double g_acc = 0.0;
__device__ int    g_cnt = 0;

// ---------------- helpers ----------------
__device__ __forceinline__ uint32_t smem_u32(const void* p) {
    uint32_t a;
    asm("{ .reg .u64 t; cvta.to.shared.u64 t, %1; cvt.u32.u64 %0, t; }" : "=r"(a) : "l"(p));
    return a;
}
__device__ __forceinline__ void ldmatrix_x4(uint32_t* r, uint32_t addr) {
    asm volatile("ldmatrix.sync.aligned.m8n8.x4.shared.b16 {%0,%1,%2,%3}, [%4];"
                 : "=r"(r[0]), "=r"(r[1]), "=r"(r[2]), "=r"(r[3]) : "r"(addr));
}
__device__ __forceinline__ void ldmatrix_x2(uint32_t* r, uint32_t addr) {
    asm volatile("ldmatrix.sync.aligned.m8n8.x2.shared.b16 {%0,%1}, [%2];"
                 : "=r"(r[0]), "=r"(r[1]) : "r"(addr));
}
__device__ __forceinline__ void mma_bf16(float* d, const uint32_t* a, const uint32_t* b) {
    asm volatile(
        "mma.sync.aligned.m16n8k16.row.col.f32.bf16.bf16.f32 "
        "{%0,%1,%2,%3}, {%4,%5,%6,%7}, {%8,%9}, {%0,%1,%2,%3};"
        : "+f"(d[0]), "+f"(d[1]), "+f"(d[2]), "+f"(d[3])
        : "r"(a[0]), "r"(a[1]), "r"(a[2]), "r"(a[3]), "r"(b[0]), "r"(b[1]));
}
__device__ __forceinline__ void cp_async16(uint32_t saddr, const void* gptr) {
    asm volatile("cp.async.cg.shared.global [%0], [%1], 16;"
                 :: "r"(saddr), "l"(gptr) : "memory");
}
#define CP_COMMIT() asm volatile("cp.async.commit_group;" ::: "memory")
#define CP_WAIT(n)  asm volatile("cp.async.wait_group %0;" :: "n"(n) : "memory")

// ================= Pass 1: normalize + transpose to g_feats =================
// grid (HW/32, 2B), block 256. Block = one b2, 32 consecutive hw.
// float4 loads: chunk = 4 hw values of one c (hw is the contiguous dim).
#define P1PITCH 257

__global__ void __launch_bounds__(256)
norm_transpose_kernel(const float* __restrict__ x, const float* __restrict__ y) {
    __shared__ float sm[32 * P1PITCH];   // [hw][c]
    const int tid  = threadIdx.x;
    const int lane = tid & 31;
    const int wrp  = tid >> 5;
    const int b2   = blockIdx.y;
    const int hw0  = blockIdx.x * 32;

    const float* src = (b2 < Bn) ? x : y;
    const int b = b2 & (Bn - 1);
    const float* base = src + ((size_t)b * Cn) * HWn + hw0;

    // 2048 float4 chunks: c = idx>>3 (0..255), hwq = idx&7 (4 hw each)
    #pragma unroll
    for (int j = 0; j < 8; j++) {
        int idx = tid + j * 256;
        int c = idx >> 3, hwq = idx & 7;
        float4 v4 = *reinterpret_cast<const float4*>(base + (size_t)c * HWn + hwq * 4);
        sm[(hwq * 4 + 0) * P1PITCH + c] = v4.x;
        sm[(hwq * 4 + 1) * P1PITCH + c] = v4.y;
        sm[(hwq * 4 + 2) * P1PITCH + c] = v4.z;
        sm[(hwq * 4 + 3) * P1PITCH + c] = v4.w;
    }
    __syncthreads();

    const float eps = 1.1920929e-07f;
    #pragma unroll
    for (int p = 0; p < 4; p++) {
        int hw = p * 8 + wrp;
        float v[4][2];
        float ss = 0.f;
        #pragma unroll
        for (int j = 0; j < 4; j++) {
            v[j][0] = sm[hw * P1PITCH + 2 * lane + 64 * j];
            v[j][1] = sm[hw * P1PITCH + 2 * lane + 64 * j + 1];
            ss += v[j][0] * v[j][0] + v[j][1] * v[j][1];
        }
        #pragma unroll
        for (int o = 16; o > 0; o >>= 1) ss += __shfl_xor_sync(0xffffffffu, ss, o);
        float scale = 1.0f / fmaxf(sqrtf(ss), eps);
        uint32_t* out = reinterpret_cast<uint32_t*>(
            g_feats + ((size_t)(hw0 + hw) * B2n + b2) * Cn);
        #pragma unroll
        for (int j = 0; j < 4; j++) {
            __nv_bfloat162 pk = __floats2bfloat162_rn(v[j][0] * scale, v[j][1] * scale);
            out[lane + 32 * j] = *reinterpret_cast<uint32_t*>(&pk);
        }
    }
}

// ================= Pass 2: symmetric Gram, quarter-stage double buffer ======
// grid 1024, block 320 (10 warps = upper-tri 32x32 blocks), occ 4.
// Stage = K-quarter: 128 rows x 64 bf16 (128B data + 16B pad = 144B pitch).
#define PITCH_S   144
#define STAGE_SZ  (128 * PITCH_S)          // 18432 B
#define SMEM_DYN  (2 * STAGE_SZ)           // 36864 B (double buffer)
#define NTHR2     320

__device__ __forceinline__ void stage_quarter(uint32_t sb, const char* gh, int tid) {
    #pragma unroll
    for (int j = 0; j < 3; j++) {              // 960 of 1024 chunks
        int idx = tid + j * NTHR2;
        int r = idx >> 3, ch = idx & 7;
        cp_async16(sb + r * PITCH_S + ch * 16, gh + r * 512 + ch * 16);
    }
    if (tid < 64) {                             // remaining 64
        int idx = 960 + tid;
        int r = idx >> 3, ch = idx & 7;
        cp_async16(sb + r * PITCH_S + ch * 16, gh + r * 512 + ch * 16);
    }
    CP_COMMIT();
}

__global__ void __launch_bounds__(NTHR2, 4)
pixel_kernel(float* __restrict__ d_out) {
    extern __shared__ __align__(16) char smem[];
    __shared__ float rs[128][4];
    __shared__ float pv[128];
    __shared__ float red[4];

    const int tid  = threadIdx.x;
    const int lane = tid & 31;
    const int w    = tid >> 5;                       // 0..9
    const int bi   = (0xE9500u >> (w << 1)) & 3;     // {0,0,0,0,1,1,1,2,2,3}
    const int bj   = (0xFB9E4u >> (w << 1)) & 3;     // {0,1,2,3,1,2,3,2,3,3}
    const int R = bi * 32, C = bj * 32;
    const bool diag = (bi == bj);

    const uint32_t sbase = smem_u32(smem);
    const char* gsrc = reinterpret_cast<const char*>(
        g_feats + (size_t)blockIdx.x * B2n * Cn);

    // prefetch quarters 0,1 into buffers 0,1
    stage_quarter(sbase,            gsrc,       tid);
    stage_quarter(sbase + STAGE_SZ, gsrc + 128, tid);

    const uint32_t a_off = (uint32_t)(lane & 15) * PITCH_S + ((lane >> 4) & 1) * 16;
    const uint32_t b_off = (uint32_t)(lane & 7)  * PITCH_S + ((lane >> 3) & 1) * 16;

    float acc[2][4][4];
    #pragma unroll
    for (int mt = 0; mt < 2; mt++)
        #pragma unroll
        for (int nt = 0; nt < 4; nt++)
            #pragma unroll
            for (int e = 0; e < 4; e++) acc[mt][nt][e] = 0.f;

    #pragma unroll
    for (int s = 0; s < 4; s++) {
        if (s < 3) CP_WAIT(1); else CP_WAIT(0);
        __syncthreads();
        const uint32_t hb = sbase + (uint32_t)(s & 1) * STAGE_SZ;
        #pragma unroll
        for (int ks = 0; ks < 4; ks++) {
            const uint32_t kb = (uint32_t)ks * 32;
            uint32_t a[2][4];
            #pragma unroll
            for (int mt = 0; mt < 2; mt++)
                ldmatrix_x4(a[mt], hb + (uint32_t)(R + mt * 16) * PITCH_S + a_off + kb);
            #pragma unroll
            for (int nt = 0; nt < 4; nt++) {
                uint32_t bfrag[2];
                ldmatrix_x2(bfrag, hb + (uint32_t)(C + nt * 8) * PITCH_S + b_off + kb);
                #pragma unroll
                for (int mt = 0; mt < 2; mt++)
                    mma_bf16(acc[mt][nt], a[mt], bfrag);
            }
        }
        __syncthreads();
        if (s < 2) stage_quarter(hb, gsrc + (s + 2) * 128, tid);
    }

    // ---- epilogue: logits = 2*sim; skip diagonal; partner = row^64 ----
    const int qrow = lane >> 2;
    const int qcol = (lane & 3) * 2;
    float psum[2][2];
    float csum[4][2];
    #pragma unroll
    for (int mt = 0; mt < 2; mt++) { psum[mt][0] = 0.f; psum[mt][1] = 0.f; }
    #pragma unroll
    for (int nt = 0; nt < 4; nt++) { csum[nt][0] = 0.f; csum[nt][1] = 0.f; }

    #pragma unroll
    for (int mt = 0; mt < 2; mt++)
        #pragma unroll
        for (int nt = 0; nt < 4; nt++)
            #pragma unroll
            for (int e = 0; e < 4; e++) {
                int row = R + mt * 16 + qrow + ((e >> 1) * 8);
                int col = C + nt * 8 + qcol + (e & 1);
                float v = 2.0f * acc[mt][nt][e];
                if (col != row) {
                    float ev = __expf(v);
                    psum[mt][e >> 1] += ev;
                    if (!diag) csum[nt][e & 1] += ev;
                }
                if (col == (row ^ 64)) { pv[row] = v; pv[col] = v; }
            }

    // row sums -> rs[.][bj]
    #pragma unroll
    for (int mt = 0; mt < 2; mt++)
        #pragma unroll
        for (int hh = 0; hh < 2; hh++) {
            float s = psum[mt][hh];
            s += __shfl_xor_sync(0xffffffffu, s, 1);
            s += __shfl_xor_sync(0xffffffffu, s, 2);
            if ((lane & 3) == 0)
                rs[R + mt * 16 + qrow + 8 * hh][bj] = s;
        }
    // col sums (off-diag) -> rs[.][bi]
    if (!diag) {
        #pragma unroll
        for (int nt = 0; nt < 4; nt++)
            #pragma unroll
            for (int p = 0; p < 2; p++) {
                float s = csum[nt][p];
                s += __shfl_xor_sync(0xffffffffu, s, 4);
                s += __shfl_xor_sync(0xffffffffu, s, 8);
                s += __shfl_xor_sync(0xffffffffu, s, 16);
                if (lane < 4)
                    rs[C + nt * 8 + (lane & 3) * 2 + p][bi] = s;
            }
    }
    __syncthreads();

    // ---- per-row loss, block reduce, global accumulate, last-CTA finish ----
    if (tid < 128) {
        float s = rs[tid][0] + rs[tid][1] + rs[tid][2] + rs[tid][3];
        float loss = pv[tid] - __logf(s);
        #pragma unroll
        for (int o = 16; o > 0; o >>= 1) loss += __shfl_xor_sync(0xffffffffu, loss, o);
        if (lane == 0) red[tid >> 5] = loss;
    }
    __syncthreads();
    if (tid == 0) {
        atomicAdd(&g_acc, (double)(red[0] + red[1] + red[2] + red[3]));
        __threadfence();
        if (atomicAdd(&g_cnt, 1) == HWn - 1) {     // last CTA: finish + reset
            __threadfence();
            double total = atomicAdd(&g_acc, 0.0);
            d_out[0] = (float)(-total / (double)((size_t)HWn * B2n));
            g_acc = 0.0;
            __threadfence();
            g_cnt = 0;
        }
    }
}

// ================= launch =================
extern "C" void kernel_launch(void* const* d_in, const int* in_sizes, int n_in,
                              void* d_out, int out_size) {
    (void)in_sizes; (void)n_in; (void)out_size;
    cudaFuncSetAttribute(pixel_kernel, cudaFuncAttributeMaxDynamicSharedMemorySize, SMEM_DYN);

    dim3 g1(HWn / 32, B2n);
    norm_transpose_kernel<<<g1, 256>>>((const float*)d_in[0], (const float*)d_in[1]);
    pixel_kernel<<<HWn, NTHR2, SMEM_DYN>>>((float*)d_out);
}

// round 11
// speedup vs baseline: 1.3474x; 1.3474x over previous
#include <cuda_runtime.h>
#include <cuda_bf16.h>
#include <cstdint>

// Problem constants
#define Bn   64
#define Cn   256
#define HWn  1024
#define B2n  128      // 2*B
// TEMPERATURE = 0.5  -> logits = 2 * sim

// ---------------- scratch (static __device__, no allocation) ----------------
__device__ __align__(16) __nv_bfloat16 g_feats[(size_t)HWn * B2n * Cn]; // 64MB
__device__ double g_acc = 0.0;
__device__ int    g_cnt = 0;

// ---------------- helpers ----------------
__device__ __forceinline__ uint32_t smem_u32(const void* p) {
    uint32_t a;
    asm("{ .reg .u64 t; cvta.to.shared.u64 t, %1; cvt.u32.u64 %0, t; }" : "=r"(a) : "l"(p));
    return a;
}
__device__ __forceinline__ void ldmatrix_x4(uint32_t* r, uint32_t addr) {
    asm volatile("ldmatrix.sync.aligned.m8n8.x4.shared.b16 {%0,%1,%2,%3}, [%4];"
                 : "=r"(r[0]), "=r"(r[1]), "=r"(r[2]), "=r"(r[3]) : "r"(addr));
}
__device__ __forceinline__ void ldmatrix_x2(uint32_t* r, uint32_t addr) {
    asm volatile("ldmatrix.sync.aligned.m8n8.x2.shared.b16 {%0,%1}, [%2];"
                 : "=r"(r[0]), "=r"(r[1]) : "r"(addr));
}
__device__ __forceinline__ void mma_bf16(float* d, const uint32_t* a, const uint32_t* b) {
    asm volatile(
        "mma.sync.aligned.m16n8k16.row.col.f32.bf16.bf16.f32 "
        "{%0,%1,%2,%3}, {%4,%5,%6,%7}, {%8,%9}, {%0,%1,%2,%3};"
        : "+f"(d[0]), "+f"(d[1]), "+f"(d[2]), "+f"(d[3])
        : "r"(a[0]), "r"(a[1]), "r"(a[2]), "r"(a[3]), "r"(b[0]), "r"(b[1]));
}
__device__ __forceinline__ void cp_async16(uint32_t saddr, const void* gptr) {
    asm volatile("cp.async.cg.shared.global [%0], [%1], 16;"
                 :: "r"(saddr), "l"(gptr) : "memory");
}
#define CP_COMMIT() asm volatile("cp.async.commit_group;" ::: "memory")
#define CP_WAIT(n)  asm volatile("cp.async.wait_group %0;" :: "n"(n) : "memory")

// ================= Pass 1 (half): normalize + transpose, R6 structure =======
// grid (16, 128), block 256. Block = one b2, 32 consecutive hw within half.
__global__ void __launch_bounds__(256)
norm_transpose_kernel(const float* __restrict__ x, const float* __restrict__ y,
                      int hw_base) {
    __shared__ float sm[32][Cn + 2];
    const int tid  = threadIdx.x;
    const int lane = tid & 31;
    const int wrp  = tid >> 5;
    const int b2   = blockIdx.y;
    const int hw0  = hw_base + blockIdx.x * 32;

    const float* src = (b2 < Bn) ? x : y;
    const int b = b2 & (Bn - 1);
    const float* base = src + ((size_t)b * Cn) * HWn + hw0;

    #pragma unroll
    for (int k = 0; k < Cn / 8; k++) {
        int c = wrp + k * 8;
        sm[lane][c] = base[(size_t)c * HWn + lane];   // coalesced: lane -> hw
    }
    __syncthreads();

    const float eps = 1.1920929e-07f;
    #pragma unroll
    for (int p = 0; p < 4; p++) {
        int hw = p * 8 + wrp;
        float v[4][2];
        float ss = 0.f;
        #pragma unroll
        for (int j = 0; j < 4; j++) {
            v[j][0] = sm[hw][2 * lane + 64 * j];
            v[j][1] = sm[hw][2 * lane + 64 * j + 1];
            ss += v[j][0] * v[j][0] + v[j][1] * v[j][1];
        }
        #pragma unroll
        for (int o = 16; o > 0; o >>= 1) ss += __shfl_xor_sync(0xffffffffu, ss, o);
        float scale = 1.0f / fmaxf(sqrtf(ss), eps);
        uint32_t* out = reinterpret_cast<uint32_t*>(
            g_feats + ((size_t)(hw0 + hw) * B2n + b2) * Cn);
        #pragma unroll
        for (int j = 0; j < 4; j++) {
            __nv_bfloat162 pk = __floats2bfloat162_rn(v[j][0] * scale, v[j][1] * scale);
            out[lane + 32 * j] = *reinterpret_cast<uint32_t*>(&pk);
        }
    }
}

// ================= Mixed kernel: producers (half B) + pixels (half A) =======
// block 320. If interleave: bid%5==4 -> pixel q=bid/5 (+pixel_base),
//                           else producer p=(bid/5)*4+(bid%5) for hw_base half.
// Else: all pixel, pixel = pixel_base + bid.
#define PITCH_H   272
#define HALF_SZ   (128 * PITCH_H)          // 34816 B
#define SMEM_DYN  (2 * HALF_SZ)            // 69632 B
#define NTHR2     320
#define P1PITCH   257

__global__ void __launch_bounds__(NTHR2, 3)
mixed_kernel(const float* __restrict__ x, const float* __restrict__ y,
             float* __restrict__ d_out, int interleave, int hw_base, int pixel_base) {
    extern __shared__ __align__(16) char smem[];

    const int tid  = threadIdx.x;
    const int lane = tid & 31;
    const int w    = tid >> 5;                 // 0..9
    const int bid  = blockIdx.x;

    int pixel = -1, prod = -1;
    if (interleave) {
        int q = bid / 5, rm = bid - q * 5;
        if (rm == 4) pixel = pixel_base + q;
        else         prod  = q * 4 + rm;       // 0..2047
    } else {
        pixel = pixel_base + bid;
    }

    if (prod >= 0) {
        // ============ producer: one b2, 32 hw of half B ============
        float* sm = reinterpret_cast<float*>(smem);      // [32][257] floats
        const int pb2 = prod >> 4;                       // 0..127
        const int hw0 = hw_base + (prod & 15) * 32;
        const float* src = (pb2 < Bn) ? x : y;
        const float* base = src + ((size_t)(pb2 & (Bn - 1)) * Cn) * HWn + hw0;

        // 8192 floats; 320 threads; lane = tid&31 constant per thread -> coalesced
        for (int idx = tid; idx < 8192; idx += NTHR2) {
            int c = idx >> 5, l = idx & 31;
            sm[l * P1PITCH + c] = base[(size_t)c * HWn + l];
        }
        __syncthreads();

        const float eps = 1.1920929e-07f;
        #pragma unroll
        for (int p = 0; p < 4; p++) {
            int hw = w + 10 * p;                         // 0..39, guard <32
            if (hw < 32) {
                float v[4][2];
                float ss = 0.f;
                #pragma unroll
                for (int j = 0; j < 4; j++) {
                    v[j][0] = sm[hw * P1PITCH + 2 * lane + 64 * j];
                    v[j][1] = sm[hw * P1PITCH + 2 * lane + 64 * j + 1];
                    ss += v[j][0] * v[j][0] + v[j][1] * v[j][1];
                }
                #pragma unroll
                for (int o = 16; o > 0; o >>= 1)
                    ss += __shfl_xor_sync(0xffffffffu, ss, o);
                float scale = 1.0f / fmaxf(sqrtf(ss), eps);
                uint32_t* out = reinterpret_cast<uint32_t*>(
                    g_feats + ((size_t)(hw0 + hw) * B2n + pb2) * Cn);
                #pragma unroll
                for (int j = 0; j < 4; j++) {
                    __nv_bfloat162 pk =
                        __floats2bfloat162_rn(v[j][0] * scale, v[j][1] * scale);
                    out[lane + 32 * j] = *reinterpret_cast<uint32_t*>(&pk);
                }
            }
        }
        return;
    }

    // ============ pixel CTA: R6-proven path ============
    __shared__ float rs[128][4];
    __shared__ float pv[128];
    __shared__ float red[4];

    const int bi = (0xE9500u >> (w << 1)) & 3;     // {0,0,0,0,1,1,1,2,2,3}
    const int bj = (0xFB9E4u >> (w << 1)) & 3;     // {0,1,2,3,1,2,3,2,3,3}
    const int R = bi * 32, C = bj * 32;
    const bool diag = (bi == bj);

    const uint32_t sbase = smem_u32(smem);
    {
        const char* gsrc = reinterpret_cast<const char*>(
            g_feats + (size_t)pixel * B2n * Cn);
        #pragma unroll
        for (int h = 0; h < 2; h++) {
            const char* gh = gsrc + h * 256;
            const uint32_t sb = sbase + h * HALF_SZ;
            #pragma unroll
            for (int j = 0; j < 6; j++) {
                int idx = tid + j * NTHR2;           // 0..1919
                int rr = idx >> 4, ch = idx & 15;
                cp_async16(sb + rr * PITCH_H + ch * 16, gh + rr * 512 + ch * 16);
            }
            if (tid < 128) {
                int idx = 1920 + tid;
                int rr = idx >> 4, ch = idx & 15;
                cp_async16(sb + rr * PITCH_H + ch * 16, gh + rr * 512 + ch * 16);
            }
            CP_COMMIT();
        }
    }

    const uint32_t a_off = (uint32_t)(lane & 15) * PITCH_H + ((lane >> 4) & 1) * 16;
    const uint32_t b_off = (uint32_t)(lane & 7)  * PITCH_H + ((lane >> 3) & 1) * 16;

    float acc[2][4][4];
    #pragma unroll
    for (int mt = 0; mt < 2; mt++)
        #pragma unroll
        for (int nt = 0; nt < 4; nt++)
            #pragma unroll
            for (int e = 0; e < 4; e++) acc[mt][nt][e] = 0.f;

    #pragma unroll
    for (int h = 0; h < 2; h++) {
        if (h == 0) CP_WAIT(1); else CP_WAIT(0);
        __syncthreads();
        const uint32_t hb = sbase + h * HALF_SZ;
        #pragma unroll
        for (int ks = 0; ks < 8; ks++) {
            const uint32_t kb = (uint32_t)ks * 32;
            uint32_t a[2][4];
            #pragma unroll
            for (int mt = 0; mt < 2; mt++)
                ldmatrix_x4(a[mt], hb + (uint32_t)(R + mt * 16) * PITCH_H + a_off + kb);
            #pragma unroll
            for (int nt = 0; nt < 4; nt++) {
                uint32_t bfrag[2];
                ldmatrix_x2(bfrag, hb + (uint32_t)(C + nt * 8) * PITCH_H + b_off + kb);
                #pragma unroll
                for (int mt = 0; mt < 2; mt++)
                    mma_bf16(acc[mt][nt], a[mt], bfrag);
            }
        }
    }

    // ---- epilogue: logits = 2*sim; skip diagonal; partner = row^64 ----
    const int qrow = lane >> 2;
    const int qcol = (lane & 3) * 2;
    float psum[2][2];
    float csum[4][2];
    #pragma unroll
    for (int mt = 0; mt < 2; mt++) { psum[mt][0] = 0.f; psum[mt][1] = 0.f; }
    #pragma unroll
    for (int nt = 0; nt < 4; nt++) { csum[nt][0] = 0.f; csum[nt][1] = 0.f; }

    #pragma unroll
    for (int mt = 0; mt < 2; mt++)
        #pragma unroll
        for (int nt = 0; nt < 4; nt++)
            #pragma unroll
            for (int e = 0; e < 4; e++) {
                int row = R + mt * 16 + qrow + ((e >> 1) * 8);
                int col = C + nt * 8 + qcol + (e & 1);
                float v = 2.0f * acc[mt][nt][e];
                if (col != row) {
                    float ev = __expf(v);
                    psum[mt][e >> 1] += ev;
                    if (!diag) csum[nt][e & 1] += ev;
                }
                if (col == (row ^ 64)) { pv[row] = v; pv[col] = v; }
            }

    // row sums -> rs[.][bj]
    #pragma unroll
    for (int mt = 0; mt < 2; mt++)
        #pragma unroll
        for (int hh = 0; hh < 2; hh++) {
            float s = psum[mt][hh];
            s += __shfl_xor_sync(0xffffffffu, s, 1);
            s += __shfl_xor_sync(0xffffffffu, s, 2);
            if ((lane & 3) == 0)
                rs[R + mt * 16 + qrow + 8 * hh][bj] = s;
        }
    // col sums (off-diag) -> rs[.][bi]
    if (!diag) {
        #pragma unroll
        for (int nt = 0; nt < 4; nt++)
            #pragma unroll
            for (int p = 0; p < 2; p++) {
                float s = csum[nt][p];
                s += __shfl_xor_sync(0xffffffffu, s, 4);
                s += __shfl_xor_sync(0xffffffffu, s, 8);
                s += __shfl_xor_sync(0xffffffffu, s, 16);
                if (lane < 4)
                    rs[C + nt * 8 + (lane & 3) * 2 + p][bi] = s;
            }
    }
    __syncthreads();

    // ---- per-row loss, block reduce, global accumulate, last-CTA finish ----
    if (tid < 128) {
        float s = rs[tid][0] + rs[tid][1] + rs[tid][2] + rs[tid][3];
        float loss = pv[tid] - __logf(s);
        #pragma unroll
        for (int o = 16; o > 0; o >>= 1) loss += __shfl_xor_sync(0xffffffffu, loss, o);
        if (lane == 0) red[tid >> 5] = loss;
    }
    __syncthreads();
    if (tid == 0) {
        atomicAdd(&g_acc, (double)(red[0] + red[1] + red[2] + red[3]));
        __threadfence();
        if (atomicAdd(&g_cnt, 1) == HWn - 1) {     // 1024th pixel CTA finishes
            __threadfence();
            double total = atomicAdd(&g_acc, 0.0);
            d_out[0] = (float)(-total / (double)((size_t)HWn * B2n));
            g_acc = 0.0;
            __threadfence();
            g_cnt = 0;
        }
    }
}

// ================= launch =================
extern "C" void kernel_launch(void* const* d_in, const int* in_sizes, int n_in,
                              void* d_out, int out_size) {
    (void)in_sizes; (void)n_in; (void)out_size;
    const float* x = (const float*)d_in[0];
    const float* y = (const float*)d_in[1];
    float* out = (float*)d_out;

    cudaFuncSetAttribute(mixed_kernel, cudaFuncAttributeMaxDynamicSharedMemorySize, SMEM_DYN);

    // k1: pass 1 for half A (hw 0..511)
    dim3 g1(16, B2n);
    norm_transpose_kernel<<<g1, 256>>>(x, y, 0);
    // k2: producers for half B (hw 512..1023) interleaved with pixels 0..511
    mixed_kernel<<<2560, NTHR2, SMEM_DYN>>>(x, y, out, 1, 512, 0);
    // k3: pixels 512..1023
    mixed_kernel<<<512, NTHR2, SMEM_DYN>>>(x, y, out, 0, 0, 512);
}

// round 12
// speedup vs baseline: 1.6077x; 1.1931x over previous
#include <cuda_runtime.h>
#include <cuda_bf16.h>
#include <cstdint>

// Problem constants
#define Bn   64
#define Cn   256
#define HWn  1024
#define B2n  128      // 2*B
// TEMPERATURE = 0.5; sim = G[ij]*rsqrt(G[ii]*G[jj]); logits = 2*sim

// ---------------- scratch (static __device__, no allocation) ----------------
__device__ __align__(16) __nv_bfloat16 g_feats[(size_t)HWn * B2n * Cn]; // 64MB raw bf16
__device__ double g_acc = 0.0;
__device__ int    g_cnt = 0;

// ---------------- helpers ----------------
__device__ __forceinline__ uint32_t smem_u32(const void* p) {
    uint32_t a;
    asm("{ .reg .u64 t; cvta.to.shared.u64 t, %1; cvt.u32.u64 %0, t; }" : "=r"(a) : "l"(p));
    return a;
}
__device__ __forceinline__ void ldmatrix_x4(uint32_t* r, uint32_t addr) {
    asm volatile("ldmatrix.sync.aligned.m8n8.x4.shared.b16 {%0,%1,%2,%3}, [%4];"
                 : "=r"(r[0]), "=r"(r[1]), "=r"(r[2]), "=r"(r[3]) : "r"(addr));
}
__device__ __forceinline__ void ldmatrix_x2(uint32_t* r, uint32_t addr) {
    asm volatile("ldmatrix.sync.aligned.m8n8.x2.shared.b16 {%0,%1}, [%2];"
                 : "=r"(r[0]), "=r"(r[1]) : "r"(addr));
}
__device__ __forceinline__ void mma_bf16(float* d, const uint32_t* a, const uint32_t* b) {
    asm volatile(
        "mma.sync.aligned.m16n8k16.row.col.f32.bf16.bf16.f32 "
        "{%0,%1,%2,%3}, {%4,%5,%6,%7}, {%8,%9}, {%0,%1,%2,%3};"
        : "+f"(d[0]), "+f"(d[1]), "+f"(d[2]), "+f"(d[3])
        : "r"(a[0]), "r"(a[1]), "r"(a[2]), "r"(a[3]), "r"(b[0]), "r"(b[1]));
}
__device__ __forceinline__ void cp_async16(uint32_t saddr, const void* gptr) {
    asm volatile("cp.async.cg.shared.global [%0], [%1], 16;"
                 :: "r"(saddr), "l"(gptr) : "memory");
}
#define CP_COMMIT() asm volatile("cp.async.commit_group;" ::: "memory")
#define CP_WAIT(n)  asm volatile("cp.async.wait_group %0;" :: "n"(n) : "memory")

// ================= Pass 1: pure transpose + bf16 convert (NO norm) ==========
// grid (32, 128), block 256. Block = one b2, 32 consecutive hw.
__global__ void __launch_bounds__(256)
transpose_kernel(const float* __restrict__ x, const float* __restrict__ y) {
    __shared__ float sm[32][260];      // pitch 260 floats (1040 B, 16B-aligned rows)
    const int tid  = threadIdx.x;
    const int lane = tid & 31;
    const int wrp  = tid >> 5;
    const int b2   = blockIdx.y;
    const int hw0  = blockIdx.x * 32;

    const float* src = (b2 < Bn) ? x : y;
    const int b = b2 & (Bn - 1);
    const float* base = src + ((size_t)b * Cn) * HWn + hw0;

    // coalesced loads: lane -> hw, warp covers c rows wrp+8k
    #pragma unroll
    for (int k = 0; k < Cn / 8; k++) {
        int c = wrp + k * 8;
        sm[lane][c] = base[(size_t)c * HWn + lane];
    }
    __syncthreads();

    // convert + store: thread owns c = 8*lane..8*lane+7 of row hw -> one STG.128
    #pragma unroll
    for (int p = 0; p < 4; p++) {
        int hw = p * 8 + wrp;
        float4 A = *reinterpret_cast<const float4*>(&sm[hw][8 * lane]);
        float4 Bv = *reinterpret_cast<const float4*>(&sm[hw][8 * lane + 4]);
        __nv_bfloat162 w0 = __floats2bfloat162_rn(A.x, A.y);
        __nv_bfloat162 w1 = __floats2bfloat162_rn(A.z, A.w);
        __nv_bfloat162 w2 = __floats2bfloat162_rn(Bv.x, Bv.y);
        __nv_bfloat162 w3 = __floats2bfloat162_rn(Bv.z, Bv.w);
        uint4 pk = make_uint4(*reinterpret_cast<uint32_t*>(&w0),
                              *reinterpret_cast<uint32_t*>(&w1),
                              *reinterpret_cast<uint32_t*>(&w2),
                              *reinterpret_cast<uint32_t*>(&w3));
        uint4* out = reinterpret_cast<uint4*>(
            g_feats + ((size_t)(hw0 + hw) * B2n + b2) * Cn);
        out[lane] = pk;                 // c = 8*lane..8*lane+7, fully coalesced
    }
}

// ================= Pass 2: symmetric raw Gram + diag rescale + softmax ======
// grid 1024, block 320 (10 warps = upper-tri 32x32 blocks). R6-proven pipeline.
#define PITCH_H   272
#define HALF_SZ   (128 * PITCH_H)          // 34816 B
#define SMEM_DYN  (2 * HALF_SZ)            // 69632 B
#define NTHR2     320

__global__ void __launch_bounds__(NTHR2, 3)
pixel_kernel(float* __restrict__ d_out) {
    extern __shared__ __align__(16) char smem[];
    __shared__ float rs[128][4];
    __shared__ float pv[128];
    __shared__ float dg[128];          // raw Gram diagonal G[ii]
    __shared__ float red[4];

    const int tid  = threadIdx.x;
    const int lane = tid & 31;
    const int w    = tid >> 5;                       // 0..9
    const int bi   = (0xE9500u >> (w << 1)) & 3;     // {0,0,0,0,1,1,1,2,2,3}
    const int bj   = (0xFB9E4u >> (w << 1)) & 3;     // {0,1,2,3,1,2,3,2,3,3}
    const int R = bi * 32, C = bj * 32;
    const bool diag = (bi == bj);

    // ---- issue cp.async for both K-halves (R6 structure) ----
    const uint32_t sbase = smem_u32(smem);
    {
        const char* gsrc = reinterpret_cast<const char*>(
            g_feats + (size_t)blockIdx.x * B2n * Cn);
        #pragma unroll
        for (int h = 0; h < 2; h++) {
            const char* gh = gsrc + h * 256;
            const uint32_t sb = sbase + h * HALF_SZ;
            #pragma unroll
            for (int j = 0; j < 6; j++) {
                int idx = tid + j * NTHR2;           // 0..1919
                int rr = idx >> 4, ch = idx & 15;
                cp_async16(sb + rr * PITCH_H + ch * 16, gh + rr * 512 + ch * 16);
            }
            if (tid < 128) {
                int idx = 1920 + tid;
                int rr = idx >> 4, ch = idx & 15;
                cp_async16(sb + rr * PITCH_H + ch * 16, gh + rr * 512 + ch * 16);
            }
            CP_COMMIT();
        }
    }

    const uint32_t a_off = (uint32_t)(lane & 15) * PITCH_H + ((lane >> 4) & 1) * 16;
    const uint32_t b_off = (uint32_t)(lane & 7)  * PITCH_H + ((lane >> 3) & 1) * 16;

    float acc[2][4][4];
    #pragma unroll
    for (int mt = 0; mt < 2; mt++)
        #pragma unroll
        for (int nt = 0; nt < 4; nt++)
            #pragma unroll
            for (int e = 0; e < 4; e++) acc[mt][nt][e] = 0.f;

    #pragma unroll
    for (int h = 0; h < 2; h++) {
        if (h == 0) CP_WAIT(1); else CP_WAIT(0);
        __syncthreads();
        const uint32_t hb = sbase + h * HALF_SZ;
        #pragma unroll
        for (int ks = 0; ks < 8; ks++) {
            const uint32_t kb = (uint32_t)ks * 32;
            uint32_t a[2][4];
            #pragma unroll
            for (int mt = 0; mt < 2; mt++)
                ldmatrix_x4(a[mt], hb + (uint32_t)(R + mt * 16) * PITCH_H + a_off + kb);
            #pragma unroll
            for (int nt = 0; nt < 4; nt++) {
                uint32_t bfrag[2];
                ldmatrix_x2(bfrag, hb + (uint32_t)(C + nt * 8) * PITCH_H + b_off + kb);
                #pragma unroll
                for (int mt = 0; mt < 2; mt++)
                    mma_bf16(acc[mt][nt], a[mt], bfrag);
            }
        }
    }

    // ---- publish raw diagonal G[ii] from diag blocks ----
    const int qrow = lane >> 2;
    const int qcol = (lane & 3) * 2;
    if (diag) {
        #pragma unroll
        for (int mt = 0; mt < 2; mt++)
            #pragma unroll
            for (int nt = 0; nt < 4; nt++)
                #pragma unroll
                for (int e = 0; e < 4; e++) {
                    int row = R + mt * 16 + qrow + ((e >> 1) * 8);
                    int col = C + nt * 8 + qcol + (e & 1);
                    if (row == col) dg[row] = acc[mt][nt][e];
                }
    }
    __syncthreads();

    // ---- rescale + epilogue: v = 2*G[ij]*rn_i*rn_j; skip diag; partner ----
    float rnc[4][2];
    #pragma unroll
    for (int nt = 0; nt < 4; nt++)
        #pragma unroll
        for (int p = 0; p < 2; p++)
            rnc[nt][p] = rsqrtf(fmaxf(dg[C + nt * 8 + qcol + p], 1e-30f));

    float psum[2][2];
    float csum[4][2];
    #pragma unroll
    for (int mt = 0; mt < 2; mt++) { psum[mt][0] = 0.f; psum[mt][1] = 0.f; }
    #pragma unroll
    for (int nt = 0; nt < 4; nt++) { csum[nt][0] = 0.f; csum[nt][1] = 0.f; }

    #pragma unroll
    for (int mt = 0; mt < 2; mt++) {
        float rnr0 = rsqrtf(fmaxf(dg[R + mt * 16 + qrow],     1e-30f));
        float rnr1 = rsqrtf(fmaxf(dg[R + mt * 16 + qrow + 8], 1e-30f));
        #pragma unroll
        for (int nt = 0; nt < 4; nt++)
            #pragma unroll
            for (int e = 0; e < 4; e++) {
                int row = R + mt * 16 + qrow + ((e >> 1) * 8);
                int col = C + nt * 8 + qcol + (e & 1);
                float rn = ((e >> 1) ? rnr1 : rnr0) * rnc[nt][e & 1];
                float v = 2.0f * acc[mt][nt][e] * rn;
                if (col != row) {
                    float ev = __expf(v);
                    psum[mt][e >> 1] += ev;
                    if (!diag) csum[nt][e & 1] += ev;
                }
                if (col == (row ^ 64)) { pv[row] = v; pv[col] = v; }
            }
    }

    // row sums -> rs[.][bj]
    #pragma unroll
    for (int mt = 0; mt < 2; mt++)
        #pragma unroll
        for (int hh = 0; hh < 2; hh++) {
            float s = psum[mt][hh];
            s += __shfl_xor_sync(0xffffffffu, s, 1);
            s += __shfl_xor_sync(0xffffffffu, s, 2);
            if ((lane & 3) == 0)
                rs[R + mt * 16 + qrow + 8 * hh][bj] = s;
        }
    // col sums (off-diag) -> rs[.][bi]
    if (!diag) {
        #pragma unroll
        for (int nt = 0; nt < 4; nt++)
            #pragma unroll
            for (int p = 0; p < 2; p++) {
                float s = csum[nt][p];
                s += __shfl_xor_sync(0xffffffffu, s, 4);
                s += __shfl_xor_sync(0xffffffffu, s, 8);
                s += __shfl_xor_sync(0xffffffffu, s, 16);
                if (lane < 4)
                    rs[C + nt * 8 + (lane & 3) * 2 + p][bi] = s;
            }
    }
    __syncthreads();

    // ---- per-row loss, block reduce, global accumulate, last-CTA finish ----
    if (tid < 128) {
        float s = rs[tid][0] + rs[tid][1] + rs[tid][2] + rs[tid][3];
        float loss = pv[tid] - __logf(s);
        #pragma unroll
        for (int o = 16; o > 0; o >>= 1) loss += __shfl_xor_sync(0xffffffffu, loss, o);
        if (lane == 0) red[tid >> 5] = loss;
    }
    __syncthreads();
    if (tid == 0) {
        atomicAdd(&g_acc, (double)(red[0] + red[1] + red[2] + red[3]));
        __threadfence();
        if (atomicAdd(&g_cnt, 1) == HWn - 1) {     // last CTA: finish + reset
            __threadfence();
            double total = atomicAdd(&g_acc, 0.0);
            d_out[0] = (float)(-total / (double)((size_t)HWn * B2n));
            g_acc = 0.0;
            __threadfence();
            g_cnt = 0;
        }
    }
}

// ================= launch =================
extern "C" void kernel_launch(void* const* d_in, const int* in_sizes, int n_in,
                              void* d_out, int out_size) {
    (void)in_sizes; (void)n_in; (void)out_size;
    cudaFuncSetAttribute(pixel_kernel, cudaFuncAttributeMaxDynamicSharedMemorySize, SMEM_DYN);

    dim3 g1(HWn / 32, B2n);
    transpose_kernel<<<g1, 256>>>((const float*)d_in[0], (const float*)d_in[1]);
    pixel_kernel<<<HWn, NTHR2, SMEM_DYN>>>((float*)d_out);
}

// round 14
// speedup vs baseline: 1.7355x; 1.0795x over previous
#include <cuda_runtime.h>
#include <cuda_bf16.h>
#include <cstdint>

// Problem constants
#define Bn   64
#define Cn   256
#define HWn  1024
#define B2n  128      // 2*B
// TEMPERATURE = 0.5  -> logits = 2 * sim

// ---------------- scratch (static __device__, no allocation) ----------------
__device__ __align__(16) uint8_t g_feats[(size_t)HWn * B2n * Cn]; // 32MB e4m3
__device__ double g_acc = 0.0;
__device__ int    g_cnt = 0;

// ---------------- helpers ----------------
__device__ __forceinline__ uint32_t smem_u32(const void* p) {
    uint32_t a;
    asm("{ .reg .u64 t; cvta.to.shared.u64 t, %1; cvt.u32.u64 %0, t; }" : "=r"(a) : "l"(p));
    return a;
}
__device__ __forceinline__ void ldmatrix_x4(uint32_t* r, uint32_t addr) {
    asm volatile("ldmatrix.sync.aligned.m8n8.x4.shared.b16 {%0,%1,%2,%3}, [%4];"
                 : "=r"(r[0]), "=r"(r[1]), "=r"(r[2]), "=r"(r[3]) : "r"(addr));
}
__device__ __forceinline__ void ldmatrix_x2(uint32_t* r, uint32_t addr) {
    asm volatile("ldmatrix.sync.aligned.m8n8.x2.shared.b16 {%0,%1}, [%2];"
                 : "=r"(r[0]), "=r"(r[1]) : "r"(addr));
}
// FP8 e4m3 MMA: D[16x8] += A[16x32] * B[8x32]^T, fp32 accum (sm_89+ PTX)
__device__ __forceinline__ void mma_e4m3(float* d, const uint32_t* a, const uint32_t* b) {
    asm volatile(
        "mma.sync.aligned.m16n8k32.row.col.f32.e4m3.e4m3.f32 "
        "{%0,%1,%2,%3}, {%4,%5,%6,%7}, {%8,%9}, {%0,%1,%2,%3};"
        : "+f"(d[0]), "+f"(d[1]), "+f"(d[2]), "+f"(d[3])
        : "r"(a[0]), "r"(a[1]), "r"(a[2]), "r"(a[3]), "r"(b[0]), "r"(b[1]));
}
__device__ __forceinline__ uint16_t cvt_e4m3x2(float hi, float lo) {
    uint16_t u;
    asm("cvt.rn.satfinite.e4m3x2.f32 %0, %1, %2;" : "=h"(u) : "f"(hi), "f"(lo));
    return u;
}
__device__ __forceinline__ void cp_async16(uint32_t saddr, const void* gptr) {
    asm volatile("cp.async.cg.shared.global [%0], [%1], 16;"
                 :: "r"(saddr), "l"(gptr) : "memory");
}
#define CP_COMMIT() asm volatile("cp.async.commit_group;" ::: "memory")
#define CP_WAIT(n)  asm volatile("cp.async.wait_group %0;" :: "n"(n) : "memory")

// ================= Pass 1: normalize + transpose -> e4m3 g_feats ============
// grid (32, 128), block 256. Block = one b2, 32 consecutive hw. R6 structure.
__global__ void __launch_bounds__(256)
norm_transpose_kernel(const float* __restrict__ x, const float* __restrict__ y) {
    __shared__ float sm[32][Cn + 2];
    const int tid  = threadIdx.x;
    const int lane = tid & 31;
    const int wrp  = tid >> 5;
    const int b2   = blockIdx.y;
    const int hw0  = blockIdx.x * 32;

    const float* src = (b2 < Bn) ? x : y;
    const int b = b2 & (Bn - 1);
    const float* base = src + ((size_t)b * Cn) * HWn + hw0;

    #pragma unroll
    for (int k = 0; k < Cn / 8; k++) {
        int c = wrp + k * 8;
        sm[lane][c] = base[(size_t)c * HWn + lane];   // coalesced: lane -> hw
    }
    __syncthreads();

    const float eps = 1.1920929e-07f;
    #pragma unroll
    for (int p = 0; p < 4; p++) {
        int hw = p * 8 + wrp;
        float v[4][2];
        float ss = 0.f;
        #pragma unroll
        for (int j = 0; j < 4; j++) {
            v[j][0] = sm[hw][2 * lane + 64 * j];
            v[j][1] = sm[hw][2 * lane + 64 * j + 1];
            ss += v[j][0] * v[j][0] + v[j][1] * v[j][1];
        }
        #pragma unroll
        for (int o = 16; o > 0; o >>= 1) ss += __shfl_xor_sync(0xffffffffu, ss, o);
        float scale = 1.0f / fmaxf(sqrtf(ss), eps);
        uint16_t* out16 = reinterpret_cast<uint16_t*>(
            g_feats + ((size_t)(hw0 + hw) * B2n + b2) * Cn);
        #pragma unroll
        for (int j = 0; j < 4; j++)
            out16[lane + 32 * j] = cvt_e4m3x2(v[j][1] * scale, v[j][0] * scale);
    }
}

// ================= Pass 2: symmetric 128x128x256 e4m3 Gram + log-softmax ====
// grid 1024, block 320 (10 warps = upper-tri 32x32 blocks).
// Tile: 128 rows x 256 e4m3 bytes (pitch 272), single stage, 8 K-steps of 32.
#define PITCH_F   272
#define TILE_F    (128 * PITCH_F)          // 34816 B
#define NTHR2     320

__global__ void __launch_bounds__(NTHR2, 3)
pixel_kernel(float* __restrict__ d_out) {
    extern __shared__ __align__(16) char smem[];
    __shared__ float rs[128][4];
    __shared__ float pv[128];
    __shared__ float red[4];

    const int tid  = threadIdx.x;
    const int lane = tid & 31;
    const int w    = tid >> 5;                       // 0..9
    const int bi   = (0xE9500u >> (w << 1)) & 3;     // {0,0,0,0,1,1,1,2,2,3}
    const int bj   = (0xFB9E4u >> (w << 1)) & 3;     // {0,1,2,3,1,2,3,2,3,3}
    const int R = bi * 32, C = bj * 32;
    const bool diag = (bi == bj);

    // ---- stage whole tile: 128 rows x 256 B (2048 16B chunks) ----
    const uint32_t sbase = smem_u32(smem);
    {
        const char* gsrc = reinterpret_cast<const char*>(
            g_feats + (size_t)blockIdx.x * B2n * Cn);
        #pragma unroll
        for (int j = 0; j < 6; j++) {
            int idx = tid + j * NTHR2;               // 0..1919
            int rr = idx >> 4, ch = idx & 15;
            cp_async16(sbase + rr * PITCH_F + ch * 16, gsrc + rr * 256 + ch * 16);
        }
        if (tid < 128) {
            int idx = 1920 + tid;
            int rr = idx >> 4, ch = idx & 15;
            cp_async16(sbase + rr * PITCH_F + ch * 16, gsrc + rr * 256 + ch * 16);
        }
        CP_COMMIT();
    }

    const uint32_t a_off = (uint32_t)(lane & 15) * PITCH_F + ((lane >> 4) & 1) * 16;
    const uint32_t b_off = (uint32_t)(lane & 7)  * PITCH_F + ((lane >> 3) & 1) * 16;

    float acc[2][4][4];
    #pragma unroll
    for (int mt = 0; mt < 2; mt++)
        #pragma unroll
        for (int nt = 0; nt < 4; nt++)
            #pragma unroll
            for (int e = 0; e < 4; e++) acc[mt][nt][e] = 0.f;

    CP_WAIT(0);
    __syncthreads();

    // 8 K-steps of 32 e4m3 (32 B each)
    #pragma unroll
    for (int ks = 0; ks < 8; ks++) {
        const uint32_t kb = (uint32_t)ks * 32;
        uint32_t a[2][4];
        #pragma unroll
        for (int mt = 0; mt < 2; mt++)
            ldmatrix_x4(a[mt], sbase + (uint32_t)(R + mt * 16) * PITCH_F + a_off + kb);
        #pragma unroll
        for (int nt = 0; nt < 4; nt++) {
            uint32_t bfrag[2];
            ldmatrix_x2(bfrag, sbase + (uint32_t)(C + nt * 8) * PITCH_F + b_off + kb);
            #pragma unroll
            for (int mt = 0; mt < 2; mt++)
                mma_e4m3(acc[mt][nt], a[mt], bfrag);
        }
    }

    // ---- epilogue: logits = 2*sim; skip diagonal; partner = row^64 ----
    const int qrow = lane >> 2;
    const int qcol = (lane & 3) * 2;
    float psum[2][2];
    float csum[4][2];
    #pragma unroll
    for (int mt = 0; mt < 2; mt++) { psum[mt][0] = 0.f; psum[mt][1] = 0.f; }
    #pragma unroll
    for (int nt = 0; nt < 4; nt++) { csum[nt][0] = 0.f; csum[nt][1] = 0.f; }

    #pragma unroll
    for (int mt = 0; mt < 2; mt++)
        #pragma unroll
        for (int nt = 0; nt < 4; nt++)
            #pragma unroll
            for (int e = 0; e < 4; e++) {
                int row = R + mt * 16 + qrow + ((e >> 1) * 8);
                int col = C + nt * 8 + qcol + (e & 1);
                float v = 2.0f * acc[mt][nt][e];
                if (col != row) {
                    float ev = __expf(v);
                    psum[mt][e >> 1] += ev;
                    if (!diag) csum[nt][e & 1] += ev;
                }
                if (col == (row ^ 64)) { pv[row] = v; pv[col] = v; }
            }

    // row sums -> rs[.][bj]
    #pragma unroll
    for (int mt = 0; mt < 2; mt++)
        #pragma unroll
        for (int hh = 0; hh < 2; hh++) {
            float s = psum[mt][hh];
            s += __shfl_xor_sync(0xffffffffu, s, 1);
            s += __shfl_xor_sync(0xffffffffu, s, 2);
            if ((lane & 3) == 0)
                rs[R + mt * 16 + qrow + 8 * hh][bj] = s;
        }
    // col sums (off-diag) -> rs[.][bi]
    if (!diag) {
        #pragma unroll
        for (int nt = 0; nt < 4; nt++)
            #pragma unroll
            for (int p = 0; p < 2; p++) {
                float s = csum[nt][p];
                s += __shfl_xor_sync(0xffffffffu, s, 4);
                s += __shfl_xor_sync(0xffffffffu, s, 8);
                s += __shfl_xor_sync(0xffffffffu, s, 16);
                if (lane < 4)
                    rs[C + nt * 8 + (lane & 3) * 2 + p][bi] = s;
            }
    }
    __syncthreads();

    // ---- per-row loss, block reduce, global accumulate, last-CTA finish ----
    if (tid < 128) {
        float s = rs[tid][0] + rs[tid][1] + rs[tid][2] + rs[tid][3];
        float loss = pv[tid] - __logf(s);
        #pragma unroll
        for (int o = 16; o > 0; o >>= 1) loss += __shfl_xor_sync(0xffffffffu, loss, o);
        if (lane == 0) red[tid >> 5] = loss;
    }
    __syncthreads();
    if (tid == 0) {
        atomicAdd(&g_acc, (double)(red[0] + red[1] + red[2] + red[3]));
        __threadfence();
        if (atomicAdd(&g_cnt, 1) == HWn - 1) {     // last CTA: finish + reset
            __threadfence();
            double total = atomicAdd(&g_acc, 0.0);
            d_out[0] = (float)(-total / (double)((size_t)HWn * B2n));
            g_acc = 0.0;
            __threadfence();
            g_cnt = 0;
        }
    }
}

// ================= launch =================
extern "C" void kernel_launch(void* const* d_in, const int* in_sizes, int n_in,
                              void* d_out, int out_size) {
    (void)in_sizes; (void)n_in; (void)out_size;
    cudaFuncSetAttribute(pixel_kernel, cudaFuncAttributeMaxDynamicSharedMemorySize, TILE_F);

    dim3 g1(HWn / 32, B2n);
    norm_transpose_kernel<<<g1, 256>>>((const float*)d_in[0], (const float*)d_in[1]);
    pixel_kernel<<<HWn, NTHR2, TILE_F>>>((float*)d_out);
}

// round 17
// speedup vs baseline: 1.9209x; 1.1068x over previous
#include <cuda_runtime.h>
#include <cuda_bf16.h>
#include <cstdint>

// Problem constants
#define Bn   64
#define Cn   256
#define HWn  1024
#define B2n  128      // 2*B
// TEMPERATURE = 0.5  -> logits = 2 * sim

// ---------------- scratch (static __device__, no allocation) ----------------
__device__ __align__(16) __nv_bfloat16 g_feats[(size_t)HWn * B2n * Cn]; // 64MB
__device__ double g_acc = 0.0;
__device__ int    g_cnt = 0;

// ---------------- helpers ----------------
__device__ __forceinline__ uint32_t smem_u32(const void* p) {
    uint32_t a;
    asm("{ .reg .u64 t; cvta.to.shared.u64 t, %1; cvt.u32.u64 %0, t; }" : "=r"(a) : "l"(p));
    return a;
}
__device__ __forceinline__ uint64_t mk_evict_first_policy() {
    uint64_t pol;
    asm("createpolicy.fractional.L2::evict_first.b64 %0, 1.0;" : "=l"(pol));
    return pol;
}
__device__ __forceinline__ uint64_t mk_evict_last_policy() {
    uint64_t pol;
    asm("createpolicy.fractional.L2::evict_last.b64 %0, 1.0;" : "=l"(pol));
    return pol;
}
__device__ __forceinline__ float ldg_stream(const float* p, uint64_t pol) {
    float v;
    asm volatile("ld.global.nc.L2::cache_hint.f32 %0, [%1], %2;"
                 : "=f"(v) : "l"(p), "l"(pol));
    return v;
}
__device__ __forceinline__ void stg_keep(uint32_t* p, uint32_t v, uint64_t pol) {
    asm volatile("st.global.L2::cache_hint.u32 [%0], %1, %2;"
                 :: "l"(p), "r"(v), "l"(pol) : "memory");
}
__device__ __forceinline__ void ldmatrix_x4(uint32_t* r, uint32_t addr) {
    asm volatile("ldmatrix.sync.aligned.m8n8.x4.shared.b16 {%0,%1,%2,%3}, [%4];"
                 : "=r"(r[0]), "=r"(r[1]), "=r"(r[2]), "=r"(r[3]) : "r"(addr));
}
__device__ __forceinline__ void ldmatrix_x2(uint32_t* r, uint32_t addr) {
    asm volatile("ldmatrix.sync.aligned.m8n8.x2.shared.b16 {%0,%1}, [%2];"
                 : "=r"(r[0]), "=r"(r[1]) : "r"(addr));
}
__device__ __forceinline__ void mma_bf16(float* d, const uint32_t* a, const uint32_t* b) {
    asm volatile(
        "mma.sync.aligned.m16n8k16.row.col.f32.bf16.bf16.f32 "
        "{%0,%1,%2,%3}, {%4,%5,%6,%7}, {%8,%9}, {%0,%1,%2,%3};"
        : "+f"(d[0]), "+f"(d[1]), "+f"(d[2]), "+f"(d[3])
        : "r"(a[0]), "r"(a[1]), "r"(a[2]), "r"(a[3]), "r"(b[0]), "r"(b[1]));
}
__device__ __forceinline__ void cp_async16(uint32_t saddr, const void* gptr) {
    asm volatile("cp.async.cg.shared.global [%0], [%1], 16;"
                 :: "r"(saddr), "l"(gptr) : "memory");
}
#define CP_COMMIT() asm volatile("cp.async.commit_group;" ::: "memory")
#define CP_WAIT(n)  asm volatile("cp.async.wait_group %0;" :: "n"(n) : "memory")

// ================= Pass 1: normalize + transpose to g_feats =================
// grid (32, 128), block 256. Block = one b2, 32 consecutive hw. R6 structure,
// L2 policy via cache_hint: inputs evict_first (streamed), scratch evict_last.
__global__ void __launch_bounds__(256)
norm_transpose_kernel(const float* __restrict__ x, const float* __restrict__ y) {
    __shared__ float sm[32][Cn + 2];
    const int tid  = threadIdx.x;
    const int lane = tid & 31;
    const int wrp  = tid >> 5;
    const int b2   = blockIdx.y;
    const int hw0  = blockIdx.x * 32;

    const float* src = (b2 < Bn) ? x : y;
    const int b = b2 & (Bn - 1);
    const float* base = src + ((size_t)b * Cn) * HWn + hw0;

    const uint64_t pol_in = mk_evict_first_policy();
    #pragma unroll
    for (int k = 0; k < Cn / 8; k++) {
        int c = wrp + k * 8;
        sm[lane][c] = ldg_stream(base + (size_t)c * HWn + lane, pol_in);  // coalesced
    }
    __syncthreads();

    const uint64_t pol_out = mk_evict_last_policy();
    const float eps = 1.1920929e-07f;
    #pragma unroll
    for (int p = 0; p < 4; p++) {
        int hw = p * 8 + wrp;
        float v[4][2];
        float ss = 0.f;
        #pragma unroll
        for (int j = 0; j < 4; j++) {
            v[j][0] = sm[hw][2 * lane + 64 * j];
            v[j][1] = sm[hw][2 * lane + 64 * j + 1];
            ss += v[j][0] * v[j][0] + v[j][1] * v[j][1];
        }
        #pragma unroll
        for (int o = 16; o > 0; o >>= 1) ss += __shfl_xor_sync(0xffffffffu, ss, o);
        float scale = 1.0f / fmaxf(sqrtf(ss), eps);
        uint32_t* out = reinterpret_cast<uint32_t*>(
            g_feats + ((size_t)(hw0 + hw) * B2n + b2) * Cn);
        #pragma unroll
        for (int j = 0; j < 4; j++) {
            __nv_bfloat162 pk = __floats2bfloat162_rn(v[j][0] * scale, v[j][1] * scale);
            stg_keep(out + lane + 32 * j, *reinterpret_cast<uint32_t*>(&pk), pol_out);
        }
    }
}

// ================= Pass 2: symmetric Gram, K-halved cp.async (R6-proven) ====
// grid 1024, block 320 (10 warps = upper-tri 32x32 blocks).
#define PITCH_H   272
#define HALF_SZ   (128 * PITCH_H)          // 34816 B
#define SMEM_DYN  (2 * HALF_SZ)            // 69632 B
#define NTHR2     320

__global__ void __launch_bounds__(NTHR2, 3)
pixel_kernel(float* __restrict__ d_out) {
    extern __shared__ __align__(16) char smem[];
    __shared__ float rs[128][4];
    __shared__ float pv[128];
    __shared__ float red[4];

    const int tid  = threadIdx.x;
    const int lane = tid & 31;
    const int w    = tid >> 5;                       // 0..9
    const int bi   = (0xE9500u >> (w << 1)) & 3;     // {0,0,0,0,1,1,1,2,2,3}
    const int bj   = (0xFB9E4u >> (w << 1)) & 3;     // {0,1,2,3,1,2,3,2,3,3}
    const int R = bi * 32, C = bj * 32;
    const bool diag = (bi == bj);

    // ---- issue cp.async for both K-halves ----
    const uint32_t sbase = smem_u32(smem);
    {
        const char* gsrc = reinterpret_cast<const char*>(
            g_feats + (size_t)blockIdx.x * B2n * Cn);
        #pragma unroll
        for (int h = 0; h < 2; h++) {
            const char* gh = gsrc + h * 256;
            const uint32_t sb = sbase + h * HALF_SZ;
            #pragma unroll
            for (int j = 0; j < 6; j++) {
                int idx = tid + j * NTHR2;           // 0..1919
                int rr = idx >> 4, ch = idx & 15;
                cp_async16(sb + rr * PITCH_H + ch * 16, gh + rr * 512 + ch * 16);
            }
            if (tid < 128) {
                int idx = 1920 + tid;
                int rr = idx >> 4, ch = idx & 15;
                cp_async16(sb + rr * PITCH_H + ch * 16, gh + rr * 512 + ch * 16);
            }
            CP_COMMIT();
        }
    }

    const uint32_t a_off = (uint32_t)(lane & 15) * PITCH_H + ((lane >> 4) & 1) * 16;
    const uint32_t b_off = (uint32_t)(lane & 7)  * PITCH_H + ((lane >> 3) & 1) * 16;

    float acc[2][4][4];
    #pragma unroll
    for (int mt = 0; mt < 2; mt++)
        #pragma unroll
        for (int nt = 0; nt < 4; nt++)
            #pragma unroll
            for (int e = 0; e < 4; e++) acc[mt][nt][e] = 0.f;

    #pragma unroll
    for (int h = 0; h < 2; h++) {
        if (h == 0) CP_WAIT(1); else CP_WAIT(0);
        __syncthreads();
        const uint32_t hb = sbase + h * HALF_SZ;
        #pragma unroll
        for (int ks = 0; ks < 8; ks++) {
            const uint32_t kb = (uint32_t)ks * 32;
            uint32_t a[2][4];
            #pragma unroll
            for (int mt = 0; mt < 2; mt++)
                ldmatrix_x4(a[mt], hb + (uint32_t)(R + mt * 16) * PITCH_H + a_off + kb);
            #pragma unroll
            for (int nt = 0; nt < 4; nt++) {
                uint32_t bfrag[2];
                ldmatrix_x2(bfrag, hb + (uint32_t)(C + nt * 8) * PITCH_H + b_off + kb);
                #pragma unroll
                for (int mt = 0; mt < 2; mt++)
                    mma_bf16(acc[mt][nt], a[mt], bfrag);
            }
        }
    }

    // ---- epilogue: logits = 2*sim; skip diagonal; partner = row^64 ----
    const int qrow = lane >> 2;
    const int qcol = (lane & 3) * 2;
    float psum[2][2];
    float csum[4][2];
    #pragma unroll
    for (int mt = 0; mt < 2; mt++) { psum[mt][0] = 0.f; psum[mt][1] = 0.f; }
    #pragma unroll
    for (int nt = 0; nt < 4; nt++) { csum[nt][0] = 0.f; csum[nt][1] = 0.f; }

    #pragma unroll
    for (int mt = 0; mt < 2; mt++)
        #pragma unroll
        for (int nt = 0; nt < 4; nt++)
            #pragma unroll
            for (int e = 0; e < 4; e++) {
                int row = R + mt * 16 + qrow + ((e >> 1) * 8);
                int col = C + nt * 8 + qcol + (e & 1);
                float v = 2.0f * acc[mt][nt][e];
                if (col != row) {
                    float ev = __expf(v);
                    psum[mt][e >> 1] += ev;
                    if (!diag) csum[nt][e & 1] += ev;
                }
                if (col == (row ^ 64)) { pv[row] = v; pv[col] = v; }
            }

    // row sums -> rs[.][bj]
    #pragma unroll
    for (int mt = 0; mt < 2; mt++)
        #pragma unroll
        for (int hh = 0; hh < 2; hh++) {
            float s = psum[mt][hh];
            s += __shfl_xor_sync(0xffffffffu, s, 1);
            s += __shfl_xor_sync(0xffffffffu, s, 2);
            if ((lane & 3) == 0)
                rs[R + mt * 16 + qrow + 8 * hh][bj] = s;
        }
    // col sums (off-diag) -> rs[.][bi]
    if (!diag) {
        #pragma unroll
        for (int nt = 0; nt < 4; nt++)
            #pragma unroll
            for (int p = 0; p < 2; p++) {
                float s = csum[nt][p];
                s += __shfl_xor_sync(0xffffffffu, s, 4);
                s += __shfl_xor_sync(0xffffffffu, s, 8);
                s += __shfl_xor_sync(0xffffffffu, s, 16);
                if (lane < 4)
                    rs[C + nt * 8 + (lane & 3) * 2 + p][bi] = s;
            }
    }
    __syncthreads();

    // ---- per-row loss, block reduce, global accumulate, last-CTA finish ----
    if (tid < 128) {
        float s = rs[tid][0] + rs[tid][1] + rs[tid][2] + rs[tid][3];
        float loss = pv[tid] - __logf(s);
        #pragma unroll
        for (int o = 16; o > 0; o >>= 1) loss += __shfl_xor_sync(0xffffffffu, loss, o);
        if (lane == 0) red[tid >> 5] = loss;
    }
    __syncthreads();
    if (tid == 0) {
        atomicAdd(&g_acc, (double)(red[0] + red[1] + red[2] + red[3]));
        __threadfence();
        if (atomicAdd(&g_cnt, 1) == HWn - 1) {     // last CTA: finish + reset
            __threadfence();
            double total = atomicAdd(&g_acc, 0.0);
            d_out[0] = (float)(-total / (double)((size_t)HWn * B2n));
            g_acc = 0.0;
            __threadfence();
            g_cnt = 0;
        }
    }
}

// ================= launch =================
extern "C" void kernel_launch(void* const* d_in, const int* in_sizes, int n_in,
                              void* d_out, int out_size) {
    (void)in_sizes; (void)n_in; (void)out_size;
    cudaFuncSetAttribute(pixel_kernel, cudaFuncAttributeMaxDynamicSharedMemorySize, SMEM_DYN);

    dim3 g1(HWn / 32, B2n);
    norm_transpose_kernel<<<g1, 256>>>((const float*)d_in[0], (const float*)d_in[1]);
    pixel_kernel<<<HWn, NTHR2, SMEM_DYN>>>((float*)d_out);
}